// round 3
// baseline (speedup 1.0000x reference)
#include <cuda_runtime.h>
#include <math.h>
#include <stdint.h>

#define BATCH   128
#define TT      504
#define TF      502      // tokens after features[:,2:]
#define TC      500      // cond frames
#define NSTEP   2000
#define NT      512      // threads in scan CTA

// ---------------- transposed-weight offsets (floats) ----------------
#define OFF_FWC    0          // (192,328)
#define OFF_FWCG   62976      // (192,192)
#define OFF_G1IH   99840      // (480,272)
#define OFF_G1HH   230400     // (480,160)
#define OFF_GLU1   307200     // (160,160)
#define OFF_G2IH   332800     // (384,240)
#define OFF_G2HH   424960     // (384,128)
#define OFF_GLU2   474112     // (128,128)
#define OFF_G3IH   490496     // (384,208)
#define OFF_G3HH   570368     // (384,128)
#define OFF_GLU3   619520     // (128,128)
#define OFF_SKIP   635904     // (128,688)
#define OFF_SKIPG  723968     // (128,128)
#define OFF_SIG    740352     // (40,128)
#define OFF_GOUT   745472     // (4,192)
#define WT_TOTAL   746240

// ---------------- device scratch (no allocations allowed) ----------------
__device__ float g_x[BATCH * TF * 64];        // fd1 output
__device__ float g_y[BATCH * TC * 128];       // conv output
__device__ float g_cond[BATCH * TC * 320];    // fd2 output
__device__ float g_gain[NSTEP * BATCH];       // precomputed gains
__device__ float g_wt[WT_TOTAL];              // transposed weights [in][out]

__device__ __forceinline__ float sigf(float x) { return 1.0f / (1.0f + expf(-x)); }

// ---------------- fused weight transpose: Wt[k*out+o] = W[o*in+k] ----------------
struct WP { const float* p[15]; };
__constant__ int T_OFF[15] = {OFF_FWC, OFF_FWCG, OFF_G1IH, OFF_G1HH, OFF_GLU1,
                              OFF_G2IH, OFF_G2HH, OFF_GLU2, OFF_G3IH, OFF_G3HH,
                              OFF_GLU3, OFF_SKIP, OFF_SKIPG, OFF_SIG, OFF_GOUT};
__constant__ int T_OUT[15] = {192, 192, 480, 480, 160, 384, 384, 128, 384, 384, 128, 128, 128, 40, 4};
__constant__ int T_IN [15] = {328, 192, 272, 160, 160, 240, 128, 128, 208, 128, 128, 688, 128, 128, 192};

__global__ void k_transpose_all(WP wp) {
    int l = blockIdx.y;
    int i = blockIdx.x * blockDim.x + threadIdx.x;
    int out = T_OUT[l], in = T_IN[l];
    if (i < out * in) {
        int o = i / in, k = i - o * in;
        g_wt[T_OFF[l] + k * out + o] = wp.p[l][i];
    }
}

// ---------------- fd1: x = tanh([f, pembed] @ fd1_w^T) ----------------
__global__ void k_fd1(const float* __restrict__ feat, const int* __restrict__ period,
                      const float* __restrict__ pembed, const float* __restrict__ fd1) {
    int bt = blockIdx.x;                 // b*TF + t
    int b = bt / TF, t = bt - b * TF;
    __shared__ float xin[32];
    int tid = threadIdx.x;
    if (tid < 20) {
        xin[tid] = feat[(b * TT + (t + 2)) * 20 + tid];
    } else if (tid < 32) {
        int per = period[b * TT + t + 2];
        per = min(max(per, 32), 254);
        xin[tid] = pembed[(per - 32) * 12 + (tid - 20)];
    }
    __syncthreads();
    float acc = 0.0f;
    const float* w = fd1 + tid * 32;
#pragma unroll
    for (int k = 0; k < 32; k++) acc += w[k] * xin[k];
    g_x[(bt) * 64 + tid] = tanhf(acc);
}

// ---------------- conv1d (kernel 3, VALID) + tanh ----------------
__global__ void k_conv(const float* __restrict__ wconv) {
    int bt = blockIdx.x;                 // b*TC + t
    int b = bt / TC, t = bt - b * TC;
    __shared__ float xin[3 * 64];
    int tid = threadIdx.x;               // oc, 128 threads
    for (int i = tid; i < 192; i += 128) {
        int kk = i / 64, ic = i - kk * 64;
        xin[kk * 64 + ic] = g_x[(b * TF + t + kk) * 64 + ic];
    }
    __syncthreads();
    float acc = 0.0f;
    const float* w = wconv + tid * 192;  // [oc][ic][kk]
#pragma unroll 8
    for (int ic = 0; ic < 64; ic++) {
        acc += w[ic * 3 + 0] * xin[0 * 64 + ic];
        acc += w[ic * 3 + 1] * xin[1 * 64 + ic];
        acc += w[ic * 3 + 2] * xin[2 * 64 + ic];
    }
    g_y[bt * 128 + tid] = tanhf(acc);
}

// ---------------- fd2: cond = tanh(y @ fd2_w^T) ----------------
__global__ void k_fd2(const float* __restrict__ fd2) {
    int bt = blockIdx.x;
    __shared__ float yin[128];
    int tid = threadIdx.x;               // 320 threads
    if (tid < 128) yin[tid] = g_y[bt * 128 + tid];
    __syncthreads();
    float acc = 0.0f;
    const float* w = fd2 + tid * 128;
#pragma unroll 8
    for (int k = 0; k < 128; k++) acc += __ldg(w + k) * yin[k];
    g_cond[(size_t)bt * 320 + tid] = tanhf(acc);
}

// ---------------- gains precompute ----------------
__global__ void k_gain(const float* __restrict__ cg_w, const float* __restrict__ cg_b) {
    int s = blockIdx.x;                  // step
    int b = threadIdx.x;                 // batch (128)
    int frame = s >> 2, sub = s & 3;
    const float* c = g_cond + ((size_t)(b * TC + frame)) * 320 + sub * 80;
    float acc = cg_b[0];
#pragma unroll 8
    for (int k = 0; k < 80; k++) acc += cg_w[k] * c[k];
    float g = 0.2f + 0.8f * sigf(acc);
    g = fminf(fmaxf(g, 0.001f), 20.0f);
    g_gain[s * BATCH + b] = g;
}

// ---------------- batched matvec: 2 batch elems, MLP-8 pipelined ----------------
// Wt is [IN][OUT] (transposed), x0/x1, y0/y1 in smem. ACT: 0=none, 1=tanh.
template <int IN, int OUT, int ACT>
__device__ __forceinline__ void matvec(const float* __restrict__ Wt,
                                       const float* __restrict__ x0, const float* __restrict__ x1,
                                       float* __restrict__ y0, float* __restrict__ y1,
                                       float* __restrict__ red) {
    constexpr int RG = OUT / 4;                      // float4 row-groups
    constexpr int S0 = NT / RG;
    constexpr int S = (S0 > 32) ? 32 : S0;           // k-slices
    int tid = threadIdx.x;
    int sl = tid / RG;
    int rg = tid - sl * RG;
    if (sl < S) {
        float4 a0 = make_float4(0.f, 0.f, 0.f, 0.f);
        float4 a1 = make_float4(0.f, 0.f, 0.f, 0.f);
        const float4* __restrict__ W4 = reinterpret_cast<const float4*>(Wt) + rg;
        int k = sl;
        // full chunks of 8: 8 independent LDG.128 front-batched -> MLP 8/warp
        for (; k + 7 * S < IN; k += 8 * S) {
            float4 w[8];
#pragma unroll
            for (int u = 0; u < 8; u++) w[u] = __ldg(&W4[(k + u * S) * RG]);
#pragma unroll
            for (int u = 0; u < 8; u++) {
                float p0 = x0[k + u * S], p1 = x1[k + u * S];
                a0.x = fmaf(w[u].x, p0, a0.x); a0.y = fmaf(w[u].y, p0, a0.y);
                a0.z = fmaf(w[u].z, p0, a0.z); a0.w = fmaf(w[u].w, p0, a0.w);
                a1.x = fmaf(w[u].x, p1, a1.x); a1.y = fmaf(w[u].y, p1, a1.y);
                a1.z = fmaf(w[u].z, p1, a1.z); a1.w = fmaf(w[u].w, p1, a1.w);
            }
        }
        for (; k < IN; k += S) {
            float4 w = __ldg(&W4[k * RG]);
            float p0 = x0[k], p1 = x1[k];
            a0.x = fmaf(w.x, p0, a0.x); a0.y = fmaf(w.y, p0, a0.y);
            a0.z = fmaf(w.z, p0, a0.z); a0.w = fmaf(w.w, p0, a0.w);
            a1.x = fmaf(w.x, p1, a1.x); a1.y = fmaf(w.y, p1, a1.y);
            a1.z = fmaf(w.z, p1, a1.z); a1.w = fmaf(w.w, p1, a1.w);
        }
        float4* r0 = reinterpret_cast<float4*>(red + sl * OUT) + rg;
        float4* r1 = reinterpret_cast<float4*>(red + 2048 + sl * OUT) + rg;
        *r0 = a0; *r1 = a1;
    }
    __syncthreads();
    // vectorized reduce: one float4 of outputs per thread
    constexpr int G = 2 * RG;
    for (int g = tid; g < G; g += NT) {
        int bb = g / RG, r = g - bb * RG;
        const float4* rr = reinterpret_cast<const float4*>(red + bb * 2048) + r;
        float4 t = make_float4(0.f, 0.f, 0.f, 0.f);
#pragma unroll
        for (int ss = 0; ss < S; ss++) {
            float4 v = rr[ss * RG];
            t.x += v.x; t.y += v.y; t.z += v.z; t.w += v.w;
        }
        if (ACT == 1) { t.x = tanhf(t.x); t.y = tanhf(t.y); t.z = tanhf(t.z); t.w = tanhf(t.w); }
        float4* y = reinterpret_cast<float4*>(bb ? y1 : y0) + r;
        *y = t;
    }
    __syncthreads();
}

// ---------------- GRU + GLU block ----------------
template <int H, int IN>
__device__ __forceinline__ void gru_glu(const float* Wih, const float* Whh, const float* Wglu,
                                        const float* x0, const float* x1,
                                        float* h0, float* h1, float* g0, float* g1,
                                        float* gi0, float* gi1, float* gh0, float* gh1,
                                        float* red) {
    matvec<IN, 3 * H, 0>(Wih, x0, x1, gi0, gi1, red);
    matvec<H, 3 * H, 0>(Whh, h0, h1, gh0, gh1, red);
    int tid = threadIdx.x;
    for (int i = tid; i < 2 * H; i += NT) {
        int bb = i / H, o = i - bb * H;
        const float* gi = bb ? gi1 : gi0;
        const float* gh = bb ? gh1 : gh0;
        float* h = bb ? h1 : h0;
        float r = sigf(gi[o] + gh[o]);
        float z = sigf(gi[H + o] + gh[H + o]);
        float n = tanhf(gi[2 * H + o] + r * gh[2 * H + o]);
        h[o] = (1.0f - z) * n + z * h[o];
    }
    __syncthreads();
    matvec<H, H, 0>(Wglu, h0, h1, gh0, gh1, red);
    for (int i = tid; i < 2 * H; i += NT) {
        int bb = i / H, o = i - bb * H;
        const float* h = bb ? h1 : h0;
        const float* u = bb ? gh1 : gh0;
        float* g = bb ? g1 : g0;
        g[o] = h[o] * sigf(u[o]);
    }
    __syncthreads();
}

// ---------------- persistent scan: each CTA owns 2 batch chains ----------------
__global__ __launch_bounds__(NT) void k_scan(const int* __restrict__ period,
                                             const float* __restrict__ gout_b,
                                             float* __restrict__ out) {
    int b0 = blockIdx.x * 2;
    __shared__ __align__(16) float exc[2][256];
    __shared__ __align__(16) float xcat[2][328];   // [0:164) state, [164:328) tmp
    __shared__ __align__(16) float s1[2][160], s2[2][128], s3[2][128];
    __shared__ __align__(16) float buf_t[2][192];  // tanh pre-glu buffer (fwc / skip)
    __shared__ __align__(16) float fwc_out[2][192];
    __shared__ __align__(16) float gi[2][480], gh[2][480];
    __shared__ __align__(16) float g1b[2][160], g2b[2][128], g3b[2][128];
    __shared__ __align__(16) float skin[2][688];   // GRU inputs + skip_in
    __shared__ __align__(16) float skipv[2][128];
    __shared__ __align__(16) float pgb[2][4];
    __shared__ __align__(16) float red[4096];
    __shared__ float sgain[2];
    __shared__ int   sper[2];
    int tid = threadIdx.x;

    // init state to zero
    for (int i = tid; i < 2 * 256; i += NT) ((float*)exc)[i] = 0.0f;
    for (int i = tid; i < 2 * 328; i += NT) ((float*)xcat)[i] = 0.0f;
    for (int i = tid; i < 2 * 160; i += NT) ((float*)s1)[i] = 0.0f;
    for (int i = tid; i < 2 * 128; i += NT) ((float*)s2)[i] = 0.0f;
    for (int i = tid; i < 2 * 128; i += NT) ((float*)s3)[i] = 0.0f;
    __syncthreads();

    int base = 0;  // exc circular base
    for (int s = 0; s < NSTEP; s++) {
        int frame = s >> 2, sub = s & 3;
        // phase0: shift state (tmp -> state) + per-step scalars
        if (tid < 4) {
            int bb = tid >> 1;
            if (tid & 1) {
                int p = period[(b0 + bb) * TT + 3 + frame];
                sper[bb] = min(max(p, 32), 254);
            } else {
                sgain[bb] = g_gain[s * BATCH + b0 + bb];
            }
        }
        if (tid < 328) {
            int bb = tid >= 164;
            int j = bb ? tid - 164 : tid;
            xcat[bb][j] = xcat[bb][164 + j];
        }
        __syncthreads();
        // phase1: build new tmp = [cond80 | pred44 | prev40]
        if (tid < 328) {
            int bb = tid >= 164;
            int j = bb ? tid - 164 : tid;
            float invg = 1.0f / (1e-5f + sgain[bb]);
            float v;
            if (j < 80) {
                v = g_cond[((size_t)((b0 + bb) * TC + frame)) * 320 + sub * 80 + j];
            } else if (j < 124) {
                int i2 = j - 80;
                int idx = 254 - sper[bb] + i2;
                if (idx >= 256) idx -= sper[bb];
                idx = max(0, min(255, idx));
                v = exc[bb][(base + idx) & 255] * invg;
            } else {
                v = exc[bb][(base + 216 + (j - 124)) & 255] * invg;
            }
            xcat[bb][164 + j] = v;
        }
        __syncthreads();

        // fwc: t = tanh(fwc_w @ xcat); fwc_out = t * sig(fwc_glu @ t)
        matvec<328, 192, 1>(g_wt + OFF_FWC, xcat[0], xcat[1], buf_t[0], buf_t[1], red);
        matvec<192, 192, 0>(g_wt + OFF_FWCG, buf_t[0], buf_t[1], gh[0], gh[1], red);
        for (int i = tid; i < 2 * 192; i += NT) {
            int bb = i / 192, j = i - bb * 192;
            fwc_out[bb][j] = buf_t[bb][j] * sigf(gh[bb][j]);
        }
        __syncthreads();

        // pg = sigmoid(gout @ fwc_out + gout_b)
        matvec<192, 4, 0>(g_wt + OFF_GOUT, fwc_out[0], fwc_out[1], pgb[0], pgb[1], red);
        if (tid < 8) {
            int bb = tid >> 2, j = tid & 3;
            pgb[bb][j] = sigf(pgb[bb][j] + gout_b[j]);
        }
        __syncthreads();

        // GRU1 input (272): [fwc_out(192) | pg0*fpitch(40) | prev(40)]
        for (int i = tid; i < 2 * 272; i += NT) {
            int bb = i / 272, j = i - bb * 272;
            float v;
            if (j < 192) v = fwc_out[bb][j];
            else if (j < 232) v = pgb[bb][0] * xcat[bb][164 + 82 + (j - 192)];
            else v = xcat[bb][164 + 124 + (j - 232)];
            skin[bb][j] = v;
        }
        __syncthreads();
        gru_glu<160, 272>(g_wt + OFF_G1IH, g_wt + OFF_G1HH, g_wt + OFF_GLU1,
                          skin[0], skin[1], s1[0], s1[1], g1b[0], g1b[1],
                          gi[0], gi[1], gh[0], gh[1], red);

        // GRU2 input (240): [g1(160) | pg1*fpitch | prev]
        for (int i = tid; i < 2 * 240; i += NT) {
            int bb = i / 240, j = i - bb * 240;
            float v;
            if (j < 160) v = g1b[bb][j];
            else if (j < 200) v = pgb[bb][1] * xcat[bb][164 + 82 + (j - 160)];
            else v = xcat[bb][164 + 124 + (j - 200)];
            skin[bb][j] = v;
        }
        __syncthreads();
        gru_glu<128, 240>(g_wt + OFF_G2IH, g_wt + OFF_G2HH, g_wt + OFF_GLU2,
                          skin[0], skin[1], s2[0], s2[1], g2b[0], g2b[1],
                          gi[0], gi[1], gh[0], gh[1], red);

        // GRU3 input (208): [g2(128) | pg2*fpitch | prev]
        for (int i = tid; i < 2 * 208; i += NT) {
            int bb = i / 208, j = i - bb * 208;
            float v;
            if (j < 128) v = g2b[bb][j];
            else if (j < 168) v = pgb[bb][2] * xcat[bb][164 + 82 + (j - 128)];
            else v = xcat[bb][164 + 124 + (j - 168)];
            skin[bb][j] = v;
        }
        __syncthreads();
        gru_glu<128, 208>(g_wt + OFF_G3IH, g_wt + OFF_G3HH, g_wt + OFF_GLU3,
                          skin[0], skin[1], s3[0], s3[1], g3b[0], g3b[1],
                          gi[0], gi[1], gh[0], gh[1], red);

        // skip_in (688): [g1 | g2 | g3 | fwc_out | pg3*fpitch | prev]
        for (int i = tid; i < 2 * 688; i += NT) {
            int bb = i / 688, j = i - bb * 688;
            float v;
            if (j < 160) v = g1b[bb][j];
            else if (j < 288) v = g2b[bb][j - 160];
            else if (j < 416) v = g3b[bb][j - 288];
            else if (j < 608) v = fwc_out[bb][j - 416];
            else if (j < 648) v = pgb[bb][3] * xcat[bb][164 + 82 + (j - 608)];
            else v = xcat[bb][164 + 124 + (j - 648)];
            skin[bb][j] = v;
        }
        __syncthreads();
        matvec<688, 128, 1>(g_wt + OFF_SKIP, skin[0], skin[1], buf_t[0], buf_t[1], red);
        matvec<128, 128, 0>(g_wt + OFF_SKIPG, buf_t[0], buf_t[1], gh[0], gh[1], red);
        for (int i = tid; i < 2 * 128; i += NT) {
            int bb = i / 128, j = i - bb * 128;
            skipv[bb][j] = buf_t[bb][j] * sigf(gh[bb][j]);
        }
        __syncthreads();

        // sig = tanh(sig_w @ skip) * gain  -> output + exc push (gi as scratch)
        matvec<128, 40, 1>(g_wt + OFF_SIG, skipv[0], skipv[1], gi[0], gi[1], red);
        for (int i = tid; i < 2 * 40; i += NT) {
            int bb = i / 40, j = i - bb * 40;
            float v = gi[bb][j] * sgain[bb];
            exc[bb][(base + j) & 255] = v;   // becomes logical [216+j] after base shift
            out[(size_t)(b0 + bb) * 80000 + s * 40 + j] = v;
        }
        __syncthreads();
        base = (base + 40) & 255;
    }
}

// ---------------- launch ----------------
extern "C" void kernel_launch(void* const* d_in, const int* in_sizes, int n_in,
                              void* d_out, int out_size) {
    const float* features = (const float*)d_in[0];
    const int*   period   = (const int*)d_in[1];
    const float* pembed   = (const float*)d_in[2];
    const float* fd1_w    = (const float*)d_in[3];
    const float* fconv1_w = (const float*)d_in[4];
    const float* fd2_w    = (const float*)d_in[5];
    const float* cg_w     = (const float*)d_in[6];
    const float* cg_b     = (const float*)d_in[7];
    const float* gout_b   = (const float*)d_in[23];
    float* out = (float*)d_out;

    WP wp;
    for (int i = 0; i < 15; i++) wp.p[i] = (const float*)d_in[8 + i];

    // launch order keeps k_scan at launch #6 so ncu (-s 5 -c 1) profiles it
    dim3 tg((130560 + 255) / 256, 15);   // max layer elems = 480*272
    k_transpose_all<<<tg, 256>>>(wp);
    k_fd1<<<BATCH * TF, 64>>>(features, period, pembed, fd1_w);
    k_conv<<<BATCH * TC, 128>>>(fconv1_w);
    k_fd2<<<BATCH * TC, 320>>>(fd2_w);
    k_gain<<<NSTEP, BATCH>>>(cg_w, cg_b);
    k_scan<<<BATCH / 2, NT>>>(period, gout_b, out);
    (void)in_sizes; (void)n_in; (void)out_size;
}

// round 4
// speedup vs baseline: 1.4143x; 1.4143x over previous
#include <cuda_runtime.h>
#include <math.h>
#include <stdint.h>

#define BATCH   128
#define TT      504
#define TF      502      // tokens after features[:,2:]
#define TC      500      // cond frames
#define NSTEP   2000
#define NT      512      // threads in scan CTA

// ---------------- transposed-weight offsets (floats) ----------------
#define OFF_FWC    0          // (192,328)
#define OFF_FWCG   62976      // (192,192)
#define OFF_G1IH   99840      // (480,272)
#define OFF_G1HH   230400     // (480,160)
#define OFF_GLU1   307200     // (160,160)
#define OFF_G2IH   332800     // (384,240)
#define OFF_G2HH   424960     // (384,128)
#define OFF_GLU2   474112     // (128,128)
#define OFF_G3IH   490496     // (384,208)
#define OFF_G3HH   570368     // (384,128)
#define OFF_GLU3   619520     // (128,128)
#define OFF_SKIP   635904     // (128,688)
#define OFF_SKIPG  723968     // (128,128)
#define OFF_SIG    740352     // (40,128)
#define OFF_GOUT   745472     // (4,192)
#define WT_TOTAL   746240

// ---------------- device scratch (no allocations allowed) ----------------
__device__ float g_x[BATCH * TF * 64];        // fd1 output
__device__ float g_y[BATCH * TC * 128];       // conv output
__device__ float g_cond[BATCH * TC * 320];    // fd2 output
__device__ float g_gain[NSTEP * BATCH];       // precomputed gains
__device__ float g_wt[WT_TOTAL];              // transposed weights [in][out]

__device__ __forceinline__ float sigf(float x) { return 1.0f / (1.0f + expf(-x)); }

// ---------------- fused weight transpose: Wt[k*out+o] = W[o*in+k] ----------------
struct WP { const float* p[15]; };
__constant__ int T_OFF[15] = {OFF_FWC, OFF_FWCG, OFF_G1IH, OFF_G1HH, OFF_GLU1,
                              OFF_G2IH, OFF_G2HH, OFF_GLU2, OFF_G3IH, OFF_G3HH,
                              OFF_GLU3, OFF_SKIP, OFF_SKIPG, OFF_SIG, OFF_GOUT};
__constant__ int T_OUT[15] = {192, 192, 480, 480, 160, 384, 384, 128, 384, 384, 128, 128, 128, 40, 4};
__constant__ int T_IN [15] = {328, 192, 272, 160, 160, 240, 128, 128, 208, 128, 128, 688, 128, 128, 192};

__global__ void k_transpose_all(WP wp) {
    int l = blockIdx.y;
    int i = blockIdx.x * blockDim.x + threadIdx.x;
    int out = T_OUT[l], in = T_IN[l];
    if (i < out * in) {
        int o = i / in, k = i - o * in;
        g_wt[T_OFF[l] + k * out + o] = wp.p[l][i];
    }
}

// ---------------- fd1: x = tanh([f, pembed] @ fd1_w^T) ----------------
__global__ void k_fd1(const float* __restrict__ feat, const int* __restrict__ period,
                      const float* __restrict__ pembed, const float* __restrict__ fd1) {
    int bt = blockIdx.x;                 // b*TF + t
    int b = bt / TF, t = bt - b * TF;
    __shared__ float xin[32];
    int tid = threadIdx.x;
    if (tid < 20) {
        xin[tid] = feat[(b * TT + (t + 2)) * 20 + tid];
    } else if (tid < 32) {
        int per = period[b * TT + t + 2];
        per = min(max(per, 32), 254);
        xin[tid] = pembed[(per - 32) * 12 + (tid - 20)];
    }
    __syncthreads();
    float acc = 0.0f;
    const float* w = fd1 + tid * 32;
#pragma unroll
    for (int k = 0; k < 32; k++) acc += w[k] * xin[k];
    g_x[(bt) * 64 + tid] = tanhf(acc);
}

// ---------------- conv1d (kernel 3, VALID) + tanh ----------------
__global__ void k_conv(const float* __restrict__ wconv) {
    int bt = blockIdx.x;                 // b*TC + t
    int b = bt / TC, t = bt - b * TC;
    __shared__ float xin[3 * 64];
    int tid = threadIdx.x;               // oc, 128 threads
    for (int i = tid; i < 192; i += 128) {
        int kk = i / 64, ic = i - kk * 64;
        xin[kk * 64 + ic] = g_x[(b * TF + t + kk) * 64 + ic];
    }
    __syncthreads();
    float acc = 0.0f;
    const float* w = wconv + tid * 192;  // [oc][ic][kk]
#pragma unroll 8
    for (int ic = 0; ic < 64; ic++) {
        acc += w[ic * 3 + 0] * xin[0 * 64 + ic];
        acc += w[ic * 3 + 1] * xin[1 * 64 + ic];
        acc += w[ic * 3 + 2] * xin[2 * 64 + ic];
    }
    g_y[bt * 128 + tid] = tanhf(acc);
}

// ---------------- fd2: cond = tanh(y @ fd2_w^T) ----------------
__global__ void k_fd2(const float* __restrict__ fd2) {
    int bt = blockIdx.x;
    __shared__ float yin[128];
    int tid = threadIdx.x;               // 320 threads
    if (tid < 128) yin[tid] = g_y[bt * 128 + tid];
    __syncthreads();
    float acc = 0.0f;
    const float* w = fd2 + tid * 128;
#pragma unroll 8
    for (int k = 0; k < 128; k++) acc += __ldg(w + k) * yin[k];
    g_cond[(size_t)bt * 320 + tid] = tanhf(acc);
}

// ---------------- gains precompute ----------------
__global__ void k_gain(const float* __restrict__ cg_w, const float* __restrict__ cg_b) {
    int s = blockIdx.x;                  // step
    int b = threadIdx.x;                 // batch (128)
    int frame = s >> 2, sub = s & 3;
    const float* c = g_cond + ((size_t)(b * TC + frame)) * 320 + sub * 80;
    float acc = cg_b[0];
#pragma unroll 8
    for (int k = 0; k < 80; k++) acc += cg_w[k] * c[k];
    float g = 0.2f + 0.8f * sigf(acc);
    g = fminf(fmaxf(g, 0.001f), 20.0f);
    g_gain[s * BATCH + b] = g;
}

// ---------------- batched matvec: y = act(Wt^T-applied), 2 batch elems ----------------
// Wt is [IN][OUT] (transposed), x0/x1, y0/y1 in smem. ACT: 0=none, 1=tanh.
// ONE change vs the 78.6ms version: unroll 4 -> unroll 16 (MLP_eff ~16, hides L2 latency)
template <int IN, int OUT, int ACT>
__device__ __forceinline__ void matvec(const float* __restrict__ Wt,
                                       const float* __restrict__ x0, const float* __restrict__ x1,
                                       float* __restrict__ y0, float* __restrict__ y1,
                                       float* __restrict__ red) {
    constexpr int RG = OUT / 4;                      // float4 row-groups
    constexpr int S0 = NT / RG;
    constexpr int S = (S0 > 32) ? 32 : S0;           // k-slices
    int tid = threadIdx.x;
    int sl = tid / RG;
    int rg = tid - sl * RG;
    if (sl < S) {
        float4 a0 = make_float4(0.f, 0.f, 0.f, 0.f);
        float4 a1 = make_float4(0.f, 0.f, 0.f, 0.f);
        const float4* __restrict__ W4 = reinterpret_cast<const float4*>(Wt) + rg;
#pragma unroll 16
        for (int k = sl; k < IN; k += S) {
            float xk0 = x0[k], xk1 = x1[k];
            float4 w = __ldg(&W4[k * RG]);
            a0.x = fmaf(w.x, xk0, a0.x); a0.y = fmaf(w.y, xk0, a0.y);
            a0.z = fmaf(w.z, xk0, a0.z); a0.w = fmaf(w.w, xk0, a0.w);
            a1.x = fmaf(w.x, xk1, a1.x); a1.y = fmaf(w.y, xk1, a1.y);
            a1.z = fmaf(w.z, xk1, a1.z); a1.w = fmaf(w.w, xk1, a1.w);
        }
        float4* r0 = reinterpret_cast<float4*>(red + sl * OUT) + rg;
        float4* r1 = reinterpret_cast<float4*>(red + 2048 + sl * OUT) + rg;
        *r0 = a0; *r1 = a1;
    }
    __syncthreads();
    for (int o = tid; o < 2 * OUT; o += NT) {
        int bb = o / OUT, j = o - bb * OUT;
        const float* r = red + bb * 2048;
        float t = 0.0f;
#pragma unroll
        for (int ss = 0; ss < S; ss++) t += r[ss * OUT + j];
        if (ACT == 1) t = tanhf(t);
        float* y = bb ? y1 : y0;
        y[j] = t;
    }
    __syncthreads();
}

// ---------------- GRU + GLU block ----------------
template <int H, int IN>
__device__ __forceinline__ void gru_glu(const float* Wih, const float* Whh, const float* Wglu,
                                        const float* x0, const float* x1,
                                        float* h0, float* h1, float* g0, float* g1,
                                        float* gi0, float* gi1, float* gh0, float* gh1,
                                        float* red) {
    matvec<IN, 3 * H, 0>(Wih, x0, x1, gi0, gi1, red);
    matvec<H, 3 * H, 0>(Whh, h0, h1, gh0, gh1, red);
    int tid = threadIdx.x;
    for (int i = tid; i < 2 * H; i += NT) {
        int bb = i / H, o = i - bb * H;
        const float* gi = bb ? gi1 : gi0;
        const float* gh = bb ? gh1 : gh0;
        float* h = bb ? h1 : h0;
        float r = sigf(gi[o] + gh[o]);
        float z = sigf(gi[H + o] + gh[H + o]);
        float n = tanhf(gi[2 * H + o] + r * gh[2 * H + o]);
        h[o] = (1.0f - z) * n + z * h[o];
    }
    __syncthreads();
    matvec<H, H, 0>(Wglu, h0, h1, gh0, gh1, red);
    for (int i = tid; i < 2 * H; i += NT) {
        int bb = i / H, o = i - bb * H;
        const float* h = bb ? h1 : h0;
        const float* u = bb ? gh1 : gh0;
        float* g = bb ? g1 : g0;
        g[o] = h[o] * sigf(u[o]);
    }
    __syncthreads();
}

// ---------------- persistent scan: each CTA owns 2 batch chains ----------------
__global__ __launch_bounds__(NT) void k_scan(const int* __restrict__ period,
                                             const float* __restrict__ gout_b,
                                             float* __restrict__ out) {
    int b0 = blockIdx.x * 2;
    __shared__ __align__(16) float exc[2][256];
    __shared__ __align__(16) float xcat[2][328];   // [0:164) state, [164:328) tmp
    __shared__ __align__(16) float s1[2][160], s2[2][128], s3[2][128];
    __shared__ __align__(16) float buf_t[2][192];  // tanh pre-glu buffer (fwc / skip)
    __shared__ __align__(16) float fwc_out[2][192];
    __shared__ __align__(16) float gi[2][480], gh[2][480];
    __shared__ __align__(16) float g1b[2][160], g2b[2][128], g3b[2][128];
    __shared__ __align__(16) float skin[2][688];   // GRU inputs + skip_in
    __shared__ __align__(16) float skipv[2][128];
    __shared__ __align__(16) float pgb[2][4];
    __shared__ __align__(16) float red[4096];
    __shared__ float sgain[2];
    __shared__ int   sper[2];
    int tid = threadIdx.x;

    // init state to zero
    for (int i = tid; i < 2 * 256; i += NT) ((float*)exc)[i] = 0.0f;
    for (int i = tid; i < 2 * 328; i += NT) ((float*)xcat)[i] = 0.0f;
    for (int i = tid; i < 2 * 160; i += NT) ((float*)s1)[i] = 0.0f;
    for (int i = tid; i < 2 * 128; i += NT) ((float*)s2)[i] = 0.0f;
    for (int i = tid; i < 2 * 128; i += NT) ((float*)s3)[i] = 0.0f;
    __syncthreads();

    int base = 0;  // exc circular base
    for (int s = 0; s < NSTEP; s++) {
        int frame = s >> 2, sub = s & 3;
        // phase0: shift state (tmp -> state) + per-step scalars
        if (tid < 4) {
            int bb = tid >> 1;
            if (tid & 1) {
                int p = period[(b0 + bb) * TT + 3 + frame];
                sper[bb] = min(max(p, 32), 254);
            } else {
                sgain[bb] = g_gain[s * BATCH + b0 + bb];
            }
        }
        if (tid < 328) {
            int bb = tid >= 164;
            int j = bb ? tid - 164 : tid;
            xcat[bb][j] = xcat[bb][164 + j];
        }
        __syncthreads();
        // phase1: build new tmp = [cond80 | pred44 | prev40]
        if (tid < 328) {
            int bb = tid >= 164;
            int j = bb ? tid - 164 : tid;
            float invg = 1.0f / (1e-5f + sgain[bb]);
            float v;
            if (j < 80) {
                v = g_cond[((size_t)((b0 + bb) * TC + frame)) * 320 + sub * 80 + j];
            } else if (j < 124) {
                int i2 = j - 80;
                int idx = 254 - sper[bb] + i2;
                if (idx >= 256) idx -= sper[bb];
                idx = max(0, min(255, idx));
                v = exc[bb][(base + idx) & 255] * invg;
            } else {
                v = exc[bb][(base + 216 + (j - 124)) & 255] * invg;
            }
            xcat[bb][164 + j] = v;
        }
        __syncthreads();

        // fwc: t = tanh(fwc_w @ xcat); fwc_out = t * sig(fwc_glu @ t)
        matvec<328, 192, 1>(g_wt + OFF_FWC, xcat[0], xcat[1], buf_t[0], buf_t[1], red);
        matvec<192, 192, 0>(g_wt + OFF_FWCG, buf_t[0], buf_t[1], gh[0], gh[1], red);
        for (int i = tid; i < 2 * 192; i += NT) {
            int bb = i / 192, j = i - bb * 192;
            fwc_out[bb][j] = buf_t[bb][j] * sigf(gh[bb][j]);
        }
        __syncthreads();

        // pg = sigmoid(gout @ fwc_out + gout_b)
        matvec<192, 4, 0>(g_wt + OFF_GOUT, fwc_out[0], fwc_out[1], pgb[0], pgb[1], red);
        if (tid < 8) {
            int bb = tid >> 2, j = tid & 3;
            pgb[bb][j] = sigf(pgb[bb][j] + gout_b[j]);
        }
        __syncthreads();

        // GRU1 input (272): [fwc_out(192) | pg0*fpitch(40) | prev(40)]
        for (int i = tid; i < 2 * 272; i += NT) {
            int bb = i / 272, j = i - bb * 272;
            float v;
            if (j < 192) v = fwc_out[bb][j];
            else if (j < 232) v = pgb[bb][0] * xcat[bb][164 + 82 + (j - 192)];
            else v = xcat[bb][164 + 124 + (j - 232)];
            skin[bb][j] = v;
        }
        __syncthreads();
        gru_glu<160, 272>(g_wt + OFF_G1IH, g_wt + OFF_G1HH, g_wt + OFF_GLU1,
                          skin[0], skin[1], s1[0], s1[1], g1b[0], g1b[1],
                          gi[0], gi[1], gh[0], gh[1], red);

        // GRU2 input (240): [g1(160) | pg1*fpitch | prev]
        for (int i = tid; i < 2 * 240; i += NT) {
            int bb = i / 240, j = i - bb * 240;
            float v;
            if (j < 160) v = g1b[bb][j];
            else if (j < 200) v = pgb[bb][1] * xcat[bb][164 + 82 + (j - 160)];
            else v = xcat[bb][164 + 124 + (j - 200)];
            skin[bb][j] = v;
        }
        __syncthreads();
        gru_glu<128, 240>(g_wt + OFF_G2IH, g_wt + OFF_G2HH, g_wt + OFF_GLU2,
                          skin[0], skin[1], s2[0], s2[1], g2b[0], g2b[1],
                          gi[0], gi[1], gh[0], gh[1], red);

        // GRU3 input (208): [g2(128) | pg2*fpitch | prev]
        for (int i = tid; i < 2 * 208; i += NT) {
            int bb = i / 208, j = i - bb * 208;
            float v;
            if (j < 128) v = g2b[bb][j];
            else if (j < 168) v = pgb[bb][2] * xcat[bb][164 + 82 + (j - 128)];
            else v = xcat[bb][164 + 124 + (j - 168)];
            skin[bb][j] = v;
        }
        __syncthreads();
        gru_glu<128, 208>(g_wt + OFF_G3IH, g_wt + OFF_G3HH, g_wt + OFF_GLU3,
                          skin[0], skin[1], s3[0], s3[1], g3b[0], g3b[1],
                          gi[0], gi[1], gh[0], gh[1], red);

        // skip_in (688): [g1 | g2 | g3 | fwc_out | pg3*fpitch | prev]
        for (int i = tid; i < 2 * 688; i += NT) {
            int bb = i / 688, j = i - bb * 688;
            float v;
            if (j < 160) v = g1b[bb][j];
            else if (j < 288) v = g2b[bb][j - 160];
            else if (j < 416) v = g3b[bb][j - 288];
            else if (j < 608) v = fwc_out[bb][j - 416];
            else if (j < 648) v = pgb[bb][3] * xcat[bb][164 + 82 + (j - 608)];
            else v = xcat[bb][164 + 124 + (j - 648)];
            skin[bb][j] = v;
        }
        __syncthreads();
        matvec<688, 128, 1>(g_wt + OFF_SKIP, skin[0], skin[1], buf_t[0], buf_t[1], red);
        matvec<128, 128, 0>(g_wt + OFF_SKIPG, buf_t[0], buf_t[1], gh[0], gh[1], red);
        for (int i = tid; i < 2 * 128; i += NT) {
            int bb = i / 128, j = i - bb * 128;
            skipv[bb][j] = buf_t[bb][j] * sigf(gh[bb][j]);
        }
        __syncthreads();

        // sig = tanh(sig_w @ skip) * gain  -> output + exc push (gi as scratch)
        matvec<128, 40, 1>(g_wt + OFF_SIG, skipv[0], skipv[1], gi[0], gi[1], red);
        for (int i = tid; i < 2 * 40; i += NT) {
            int bb = i / 40, j = i - bb * 40;
            float v = gi[bb][j] * sgain[bb];
            exc[bb][(base + j) & 255] = v;   // becomes logical [216+j] after base shift
            out[(size_t)(b0 + bb) * 80000 + s * 40 + j] = v;
        }
        __syncthreads();
        base = (base + 40) & 255;
    }
}

// ---------------- launch ----------------
extern "C" void kernel_launch(void* const* d_in, const int* in_sizes, int n_in,
                              void* d_out, int out_size) {
    const float* features = (const float*)d_in[0];
    const int*   period   = (const int*)d_in[1];
    const float* pembed   = (const float*)d_in[2];
    const float* fd1_w    = (const float*)d_in[3];
    const float* fconv1_w = (const float*)d_in[4];
    const float* fd2_w    = (const float*)d_in[5];
    const float* cg_w     = (const float*)d_in[6];
    const float* cg_b     = (const float*)d_in[7];
    const float* gout_b   = (const float*)d_in[23];
    float* out = (float*)d_out;

    WP wp;
    for (int i = 0; i < 15; i++) wp.p[i] = (const float*)d_in[8 + i];

    // launch order keeps k_scan at launch #6 so ncu (-s 5 -c 1) profiles it
    dim3 tg((130560 + 255) / 256, 15);   // max layer elems = 480*272
    k_transpose_all<<<tg, 256>>>(wp);
    k_fd1<<<BATCH * TF, 64>>>(features, period, pembed, fd1_w);
    k_conv<<<BATCH * TC, 128>>>(fconv1_w);
    k_fd2<<<BATCH * TC, 320>>>(fd2_w);
    k_gain<<<NSTEP, BATCH>>>(cg_w, cg_b);
    k_scan<<<BATCH / 2, NT>>>(period, gout_b, out);
    (void)in_sizes; (void)n_in; (void)out_size;
}